// round 4
// baseline (speedup 1.0000x reference)
#include <cuda_runtime.h>
#include <math.h>

#define BB 256
#define HH 28
#define WW 28

typedef unsigned long long u64;

// packed f32x2 fma: acc.{lo,hi} += a.{lo,hi} * b.{lo,hi}
__device__ __forceinline__ void ffma2(u64& acc, u64 a, u64 b) {
    asm("fma.rn.f32x2 %0, %1, %2, %0;" : "+l"(acc) : "l"(a), "l"(b));
}
__device__ __forceinline__ float f2sum(u64 v) {
    float lo, hi;
    asm("mov.b64 {%0, %1}, %2;" : "=f"(lo), "=f"(hi) : "l"(v));
    return lo + hi;
}

// Scratch (device globals: allocation-free rule). Zero-initialized at module
// load; g_h2p borders are never written by any kernel -> stay zero (padding).
__device__ float g_h1p[BB*30*30*32];   // conv1 out, NHWC padded, zero border
__device__ float g_offs[BB*28*28*18];  // p_conv offsets, NHWC
__device__ float g_h2p[BB*30*30*32];   // deform out, NHWC padded, zero border
__device__ float g_part[BB*7*64];      // partial pooled sums of relu(conv3)

// ---------------------------------------------------------------------------
// K1: conv1(3->32, pad1) + relu + bn1  -> g_h1p (NHWC padded, zero borders)
// ---------------------------------------------------------------------------
__global__ void k1_conv1(const float* __restrict__ x, const float* __restrict__ w1,
                         const float* __restrict__ g1, const float* __restrict__ b1,
                         const float* __restrict__ m1, const float* __restrict__ v1) {
    __shared__ float ws[27*32];          // [c*9+tap][o]
    int tid = threadIdx.x;
    for (int i = tid; i < 27*32; i += blockDim.x) {
        int tap = i >> 5, o = i & 31;
        ws[i] = w1[o*27 + tap];
    }
    __syncthreads();
    int wg   = blockIdx.x*8 + (tid >> 5);
    int lane = tid & 31;
    int b = wg / 900, rem = wg % 900;
    int yp = rem / 30, xp = rem % 30;
    float* dst = &g_h1p[((b*30+yp)*30+xp)*32 + lane];
    if (yp == 0 || yp == 29 || xp == 0 || xp == 29) { *dst = 0.f; return; }
    int y = yp - 1, x0 = xp - 1;
    float acc = 0.f;
    #pragma unroll
    for (int c = 0; c < 3; c++) {
        #pragma unroll
        for (int ky = 0; ky < 3; ky++) {
            int iy = y + ky - 1;
            #pragma unroll
            for (int kx = 0; kx < 3; kx++) {
                int ix = x0 + kx - 1;
                float xv = 0.f;
                if (iy >= 0 && iy < 28 && ix >= 0 && ix < 28)
                    xv = __ldg(&x[((b*3+c)*28+iy)*28+ix]);
                acc = fmaf(xv, ws[(c*9+ky*3+kx)*32 + lane], acc);
            }
        }
    }
    acc = fmaxf(acc, 0.f);
    float inv = g1[lane] * rsqrtf(v1[lane] + 1e-5f);
    *dst = acc * inv + (b1[lane] - m1[lane]*inv);
}

// ---------------------------------------------------------------------------
// K2: p_conv(32->18, pad1) + bias -> g_offs
// block = (image, 4-row strip), 128 thr; c-pair packed f32x2, float4 act loads
// dyn smem: wsh2 float2[16*9*32] (36864B) + ash 6*30*32 (23040B) = 59904B
// ---------------------------------------------------------------------------
__global__ void k2_pconv(const float* __restrict__ wp, const float* __restrict__ bp) {
    extern __shared__ float sm2[];
    float2* wsh = (float2*)sm2;          // [(c2*9+t)*32 + lane] = (w[c=2c2], w[c=2c2+1])
    float*  ash = sm2 + 2*16*9*32;       // [ry][x][c], 6x30x32
    int tid = threadIdx.x;
    int b = blockIdx.x / 7, strip = blockIdx.x % 7;
    for (int i = tid; i < 16*9*32; i += 128) {
        int lane = i & 31, t = (i >> 5) % 9, c2 = i / 288;
        if (lane < 18)
            wsh[i] = make_float2(wp[lane*288 + (2*c2)*9 + t], wp[lane*288 + (2*c2+1)*9 + t]);
        else
            wsh[i] = make_float2(0.f, 0.f);
    }
    const float* src = &g_h1p[(b*30 + strip*4)*30*32];
    for (int i = tid; i < 6*30*32; i += 128) ash[i] = src[i];
    __syncthreads();

    int warp = tid >> 5, lane = tid & 31;
    int y = strip*4 + warp;
    float bpv = (lane < 18) ? bp[lane] : 0.f;
    for (int x0 = 0; x0 < 28; x0 += 7) {
        u64 acc[7] = {0,0,0,0,0,0,0};
        #pragma unroll
        for (int c4 = 0; c4 < 8; c4++) {
            #pragma unroll
            for (int t = 0; t < 9; t++) {
                u64 wa = ((const u64*)&wsh[((2*c4)*9 + t)*32 + lane])[0];
                u64 wb = ((const u64*)&wsh[((2*c4+1)*9 + t)*32 + lane])[0];
                const float* ap = &ash[((warp + t/3)*30 + x0 + (t%3))*32 + c4*4];
                #pragma unroll
                for (int i = 0; i < 7; i++) {
                    ulonglong2 a = *(const ulonglong2*)(ap + i*32);
                    ffma2(acc[i], a.x, wa);
                    ffma2(acc[i], a.y, wb);
                }
            }
        }
        if (lane < 18) {
            #pragma unroll
            for (int i = 0; i < 7; i++)
                g_offs[((b*28+y)*28 + x0 + i)*18 + lane] = f2sum(acc[i]) + bpv;
        }
    }
}

// ---------------------------------------------------------------------------
// K3: fused deformable sample + 9pt conv (32->32) + relu + bn2 -> g_h2p
// block = (image, 2-row strip of 56 px), 256 threads.
// Phase A: 8 warps sample 7 px each (lane = in channel) -> xsh[56][288]
// Phase B: c-pair packed f32x2 GEMM, 7-px tile per warp (lane = out channel)
// dyn smem: wsh2 float2[144*32] (36864B) + xsh 56*288 (64512B) = 101376B
// ---------------------------------------------------------------------------
__global__ void k3_deform(const float* __restrict__ w2, const float* __restrict__ g2,
                          const float* __restrict__ b2_, const float* __restrict__ m2,
                          const float* __restrict__ v2) {
    extern __shared__ float sm3[];
    float2* wsh = (float2*)sm3;          // [nc2*32 + lane] pairs over consecutive nc
    float*  xsh = sm3 + 9216;            // [pl*288 + n*32 + c]
    int tid = threadIdx.x;
    int b = blockIdx.x / 14, strip = blockIdx.x % 14;
    int y0 = strip*2;
    // xsh index nc = n*32 + c ; weight for (o, nc): w2[o*288 + c*9 + n]
    for (int i = tid; i < 144*32; i += 256) {
        int lane = i & 31, nc2 = i >> 5;
        int n = nc2 >> 4, c = (2*nc2) & 31;
        wsh[i] = make_float2(w2[lane*288 + c*9 + n], w2[lane*288 + (c+1)*9 + n]);
    }
    int warp = tid >> 5, lane = tid & 31;
    const float* img = &g_h1p[b*900*32];

    // Phase A: bilinear sampling
    for (int k = 0; k < 7; k++) {
        int pl = warp + k*8;             // 0..55
        int y = y0 + pl/28, x = pl%28;
        const float* offp = &g_offs[((b*28+y)*28+x)*18];
        #pragma unroll
        for (int n = 0; n < 9; n++) {
            float oy = offp[n];
            float ox = offp[9+n];
            float pyr = (float)(y + n/3) + oy;
            float pxr = (float)(x + n%3) + ox;
            float fy = floorf(pyr), fx = floorf(pxr);
            float qy0 = fminf(fmaxf(fy,       0.f), 29.f);
            float qy1 = fminf(fmaxf(fy + 1.f, 0.f), 29.f);
            float qx0 = fminf(fmaxf(fx,       0.f), 29.f);
            float qx1 = fminf(fmaxf(fx + 1.f, 0.f), 29.f);
            float pyc = fminf(fmaxf(pyr, 0.f), 29.f);
            float pxc = fminf(fmaxf(pxr, 0.f), 29.f);
            float glt = (1.f + (qy0 - pyc)) * (1.f + (qx0 - pxc));
            float grb = (1.f - (qy1 - pyc)) * (1.f - (qx1 - pxc));
            float glb = (1.f + (qy0 - pyc)) * (1.f - (qx1 - pxc));
            float grt = (1.f - (qy1 - pyc)) * (1.f + (qx0 - pxc));
            int iy0 = (int)qy0, iy1 = (int)qy1, ix0 = (int)qx0, ix1 = (int)qx1;
            float v00 = img[(iy0*30+ix0)*32 + lane];
            float v11 = img[(iy1*30+ix1)*32 + lane];
            float v01 = img[(iy0*30+ix1)*32 + lane];
            float v10 = img[(iy1*30+ix0)*32 + lane];
            xsh[pl*288 + n*32 + lane] = glt*v00 + grb*v11 + glb*v01 + grt*v10;
        }
    }
    __syncthreads();

    // Phase B: 288 -> 32 GEMM, packed c-pairs
    int pbase = warp*7;
    u64 acc[7] = {0,0,0,0,0,0,0};
    const float* xp0 = &xsh[pbase*288];
    for (int nc4 = 0; nc4 < 72; nc4++) {
        u64 wa = ((const u64*)&wsh[(2*nc4)*32 + lane])[0];
        u64 wb = ((const u64*)&wsh[(2*nc4+1)*32 + lane])[0];
        #pragma unroll
        for (int i = 0; i < 7; i++) {
            ulonglong2 a = *(const ulonglong2*)(xp0 + i*288 + nc4*4);
            ffma2(acc[i], a.x, wa);
            ffma2(acc[i], a.y, wb);
        }
    }
    float inv = g2[lane] * rsqrtf(v2[lane] + 1e-5f);
    float sh  = b2_[lane] - m2[lane]*inv;
    #pragma unroll
    for (int i = 0; i < 7; i++) {
        int px = pbase + i;
        int y = y0 + px/28, x = px%28;
        g_h2p[((b*30+y+1)*30 + x+1)*32 + lane] = fmaxf(f2sum(acc[i]), 0.f)*inv + sh;
    }
}

// ---------------------------------------------------------------------------
// K4: conv3(32->64, pad1) + relu + partial pooled sum (bn folded into head)
// block = (image, 4-row strip), 128 threads. Both o-halves per lane.
// c-pair packed f32x2, float4 act + float4 weight loads.
// dyn smem: wsh4 float4[16*9*32] (73728B) + ash 6*30*32 (23040B) = 96768B
// ---------------------------------------------------------------------------
__global__ void k4_conv3(const float* __restrict__ w3) {
    extern __shared__ float sm4[];
    float4* wsh = (float4*)sm4;          // [(c2*9+t)*32+lane] = (w[o=l][2c2],w[o=l][2c2+1],w[o=l+32][2c2],w[o=l+32][2c2+1])
    float*  ash = sm4 + 4*16*9*32;       // [ry][x][c], 6x30x32
    __shared__ float red[64];
    int tid = threadIdx.x;
    int b = blockIdx.x / 7, strip = blockIdx.x % 7;
    for (int i = tid; i < 16*9*32; i += 128) {
        int lane = i & 31, t = (i >> 5) % 9, c2 = i / 288;
        wsh[i] = make_float4(w3[lane*288      + (2*c2)*9 + t], w3[lane*288      + (2*c2+1)*9 + t],
                             w3[(lane+32)*288 + (2*c2)*9 + t], w3[(lane+32)*288 + (2*c2+1)*9 + t]);
    }
    const float* src = &g_h2p[(b*30 + strip*4)*30*32];
    for (int i = tid; i < 6*30*32; i += 128) ash[i] = src[i];
    if (tid < 64) red[tid] = 0.f;
    __syncthreads();

    int warp = tid >> 5, lane = tid & 31;
    float s0 = 0.f, s1 = 0.f;
    for (int x0 = 0; x0 < 28; x0 += 7) {
        u64 acc0[7] = {0,0,0,0,0,0,0};   // o = lane, even/odd c partials
        u64 acc1[7] = {0,0,0,0,0,0,0};   // o = lane+32
        #pragma unroll
        for (int c4 = 0; c4 < 8; c4++) {
            #pragma unroll
            for (int t = 0; t < 9; t++) {
                ulonglong2 wa = *(const ulonglong2*)&wsh[((2*c4)*9 + t)*32 + lane];
                ulonglong2 wb = *(const ulonglong2*)&wsh[((2*c4+1)*9 + t)*32 + lane];
                const float* ap = &ash[((warp + t/3)*30 + x0 + (t%3))*32 + c4*4];
                #pragma unroll
                for (int i = 0; i < 7; i++) {
                    ulonglong2 a = *(const ulonglong2*)(ap + i*32);
                    ffma2(acc0[i], a.x, wa.x);
                    ffma2(acc1[i], a.x, wa.y);
                    ffma2(acc0[i], a.y, wb.x);
                    ffma2(acc1[i], a.y, wb.y);
                }
            }
        }
        #pragma unroll
        for (int i = 0; i < 7; i++) {
            s0 += fmaxf(f2sum(acc0[i]), 0.f);
            s1 += fmaxf(f2sum(acc1[i]), 0.f);
        }
    }
    atomicAdd(&red[lane],      s0);
    atomicAdd(&red[lane + 32], s1);
    __syncthreads();
    if (tid < 64) g_part[(b*7+strip)*64 + tid] = red[tid];
}

// ---------------------------------------------------------------------------
// K5: reduce partials -> mean -> bn3 -> linear(64->10) -> log_softmax
// ---------------------------------------------------------------------------
__global__ void k5_head(const float* __restrict__ g3, const float* __restrict__ b3,
                        const float* __restrict__ m3, const float* __restrict__ v3,
                        const float* __restrict__ wc, const float* __restrict__ bc,
                        float* __restrict__ out) {
    __shared__ float hsh[64];
    __shared__ float lg[10];
    int b = blockIdx.x, tid = threadIdx.x;
    if (tid < 64) {
        float s = 0.f;
        for (int k = 0; k < 7; k++) s += g_part[(b*7+k)*64 + tid];
        s *= (1.f/784.f);
        float inv = g3[tid] * rsqrtf(v3[tid] + 1e-5f);
        hsh[tid] = s * inv + (b3[tid] - m3[tid]*inv);
    }
    __syncthreads();
    if (tid < 10) {
        float acc = bc[tid];
        for (int o = 0; o < 64; o++) acc = fmaf(hsh[o], wc[tid*64 + o], acc);
        lg[tid] = acc;
    }
    __syncthreads();
    if (tid < 10) {
        float mx = -1e30f;
        for (int j = 0; j < 10; j++) mx = fmaxf(mx, lg[j]);
        float se = 0.f;
        for (int j = 0; j < 10; j++) se += expf(lg[j] - mx);
        out[b*10 + tid] = lg[tid] - mx - logf(se);
    }
}

// ---------------------------------------------------------------------------
extern "C" void kernel_launch(void* const* d_in, const int* in_sizes, int n_in,
                              void* d_out, int out_size) {
    const float* x  = (const float*)d_in[0];
    const float* w1 = (const float*)d_in[1];
    const float* g1 = (const float*)d_in[2];
    const float* b1 = (const float*)d_in[3];
    const float* m1 = (const float*)d_in[4];
    const float* v1 = (const float*)d_in[5];
    const float* wp = (const float*)d_in[6];
    const float* bp = (const float*)d_in[7];
    const float* w2 = (const float*)d_in[8];
    const float* g2 = (const float*)d_in[9];
    const float* b2 = (const float*)d_in[10];
    const float* m2 = (const float*)d_in[11];
    const float* v2 = (const float*)d_in[12];
    const float* w3 = (const float*)d_in[13];
    const float* g3 = (const float*)d_in[14];
    const float* b3 = (const float*)d_in[15];
    const float* m3 = (const float*)d_in[16];
    const float* v3 = (const float*)d_in[17];
    const float* wc = (const float*)d_in[18];
    const float* bc = (const float*)d_in[19];

    cudaFuncSetAttribute(k2_pconv,  cudaFuncAttributeMaxDynamicSharedMemorySize, 59904);
    cudaFuncSetAttribute(k3_deform, cudaFuncAttributeMaxDynamicSharedMemorySize, 101376);
    cudaFuncSetAttribute(k4_conv3,  cudaFuncAttributeMaxDynamicSharedMemorySize, 96768);

    k1_conv1<<<28800, 256>>>(x, w1, g1, b1, m1, v1);
    k2_pconv<<<BB*7, 128, 59904>>>(wp, bp);
    k3_deform<<<BB*14, 256, 101376>>>(w2, g2, b2, m2, v2);
    k4_conv3<<<BB*7, 128, 96768>>>(w3);
    k5_head<<<BB, 64>>>(g3, b3, m3, v3, wc, bc, (float*)d_out);
}

// round 5
// speedup vs baseline: 1.0078x; 1.0078x over previous
#include <cuda_runtime.h>
#include <math.h>

#define BB 256
#define HH 28
#define WW 28

// Scratch (device globals: allocation-free rule). Zero-initialized at module
// load; g_h2p borders are never written by any kernel -> stay zero (padding).
__device__ float g_h1p[BB*30*30*32];   // conv1 out, NHWC padded, zero border
__device__ float g_offs[BB*28*28*18];  // p_conv offsets, NHWC
__device__ float g_h2p[BB*30*30*32];   // deform out, NHWC padded, zero border
__device__ float g_part[BB*7*64];      // partial pooled sums of relu(conv3)

// ---------------------------------------------------------------------------
// K1: conv1(3->32, pad1) + relu + bn1  -> g_h1p (NHWC padded, zero borders)
// ---------------------------------------------------------------------------
__global__ void k1_conv1(const float* __restrict__ x, const float* __restrict__ w1,
                         const float* __restrict__ g1, const float* __restrict__ b1,
                         const float* __restrict__ m1, const float* __restrict__ v1) {
    __shared__ float ws[27*32];          // [c*9+tap][o]
    int tid = threadIdx.x;
    for (int i = tid; i < 27*32; i += blockDim.x) {
        int tap = i >> 5, o = i & 31;
        ws[i] = w1[o*27 + tap];
    }
    __syncthreads();
    int wg   = blockIdx.x*8 + (tid >> 5);
    int lane = tid & 31;
    int b = wg / 900, rem = wg % 900;
    int yp = rem / 30, xp = rem % 30;
    float* dst = &g_h1p[((b*30+yp)*30+xp)*32 + lane];
    if (yp == 0 || yp == 29 || xp == 0 || xp == 29) { *dst = 0.f; return; }
    int y = yp - 1, x0 = xp - 1;
    float acc = 0.f;
    #pragma unroll
    for (int c = 0; c < 3; c++) {
        #pragma unroll
        for (int ky = 0; ky < 3; ky++) {
            int iy = y + ky - 1;
            #pragma unroll
            for (int kx = 0; kx < 3; kx++) {
                int ix = x0 + kx - 1;
                float xv = 0.f;
                if (iy >= 0 && iy < 28 && ix >= 0 && ix < 28)
                    xv = __ldg(&x[((b*3+c)*28+iy)*28+ix]);
                acc = fmaf(xv, ws[(c*9+ky*3+kx)*32 + lane], acc);
            }
        }
    }
    acc = fmaxf(acc, 0.f);
    float inv = g1[lane] * rsqrtf(v1[lane] + 1e-5f);
    *dst = acc * inv + (b1[lane] - m1[lane]*inv);
}

// ---------------------------------------------------------------------------
// K2: p_conv(32->18, pad1) + bias -> g_offs
// block = (image, 4-row strip), 128 thr; float4 act + float4 weight loads,
// scalar FFMA. warp = output row; 7-px register tile; lane = o (0..17 live).
// dyn smem: wsh float4[8*9*32] (36864B) + ash 6*30*32 (23040B) = 59904B
// ---------------------------------------------------------------------------
__global__ void k2_pconv(const float* __restrict__ wp, const float* __restrict__ bp) {
    extern __shared__ float sm2[];
    float4* wsh = (float4*)sm2;          // [(c4*9+t)*32 + lane] = w[o=lane][4c4..4c4+3]
    float*  ash = sm2 + 4*8*9*32;        // [ry][x][c], 6x30x32
    int tid = threadIdx.x;
    int b = blockIdx.x / 7, strip = blockIdx.x % 7;
    for (int i = tid; i < 8*9*32; i += 128) {
        int lane = i & 31, t = (i >> 5) % 9, c4 = i / 288;
        if (lane < 18)
            wsh[i] = make_float4(wp[lane*288 + (4*c4+0)*9 + t], wp[lane*288 + (4*c4+1)*9 + t],
                                 wp[lane*288 + (4*c4+2)*9 + t], wp[lane*288 + (4*c4+3)*9 + t]);
        else
            wsh[i] = make_float4(0.f, 0.f, 0.f, 0.f);
    }
    const float* src = &g_h1p[(b*30 + strip*4)*30*32];
    for (int i = tid; i < 6*30*32; i += 128) ash[i] = src[i];
    __syncthreads();

    int warp = tid >> 5, lane = tid & 31;
    int y = strip*4 + warp;
    float bpv = (lane < 18) ? bp[lane] : 0.f;
    for (int x0 = 0; x0 < 28; x0 += 7) {
        float acc[7] = {0,0,0,0,0,0,0};
        for (int t = 0; t < 9; t++) {
            int ty = t/3, tx = t%3;
            const float4* ap = (const float4*)&ash[((warp + ty)*30 + x0 + tx)*32];
            #pragma unroll
            for (int c4 = 0; c4 < 8; c4++) {
                float4 w = wsh[(c4*9+t)*32 + lane];
                #pragma unroll
                for (int i = 0; i < 7; i++) {
                    float4 a = ap[i*8 + c4];
                    acc[i] = fmaf(a.x, w.x, acc[i]);
                    acc[i] = fmaf(a.y, w.y, acc[i]);
                    acc[i] = fmaf(a.z, w.z, acc[i]);
                    acc[i] = fmaf(a.w, w.w, acc[i]);
                }
            }
        }
        if (lane < 18) {
            #pragma unroll
            for (int i = 0; i < 7; i++)
                g_offs[((b*28+y)*28 + x0 + i)*18 + lane] = acc[i] + bpv;
        }
    }
}

// ---------------------------------------------------------------------------
// K3: fused deformable sample + 9pt conv (32->32) + relu + bn2 -> g_h2p
// block = (image, 2-row strip of 56 px), 256 threads.
// Phase A: 8 warps sample 7 px each (lane = in channel) -> xsh[56][288]
// Phase B: float4 x + float4 w loads, scalar FFMA; 7-px tile (lane = out ch)
// dyn smem: wsh float4[72*32] (36864B) + xsh 56*288 (64512B) = 101376B
// ---------------------------------------------------------------------------
__global__ void k3_deform(const float* __restrict__ w2, const float* __restrict__ g2,
                          const float* __restrict__ b2_, const float* __restrict__ m2,
                          const float* __restrict__ v2) {
    extern __shared__ float sm3[];
    float4* wsh = (float4*)sm3;          // [nc4*32 + lane] = w[o=lane][nc4*4 .. +3]
    float*  xsh = sm3 + 9216;            // [pl*288 + n*32 + c]
    int tid = threadIdx.x;
    int b = blockIdx.x / 14, strip = blockIdx.x % 14;
    int y0 = strip*2;
    // xsh index nc = n*32 + c ; weight for (o, nc): w2[o*288 + c*9 + n]
    for (int i = tid; i < 72*32; i += 256) {
        int lane = i & 31, nc4 = i >> 5;
        int n = nc4 >> 3, c = (nc4 & 7)*4;
        wsh[i] = make_float4(w2[lane*288 + (c+0)*9 + n], w2[lane*288 + (c+1)*9 + n],
                             w2[lane*288 + (c+2)*9 + n], w2[lane*288 + (c+3)*9 + n]);
    }
    int warp = tid >> 5, lane = tid & 31;
    const float* img = &g_h1p[b*900*32];

    // Phase A: bilinear sampling
    for (int k = 0; k < 7; k++) {
        int pl = warp + k*8;             // 0..55
        int y = y0 + pl/28, x = pl%28;
        const float* offp = &g_offs[((b*28+y)*28+x)*18];
        #pragma unroll
        for (int n = 0; n < 9; n++) {
            float oy = offp[n];
            float ox = offp[9+n];
            float pyr = (float)(y + n/3) + oy;
            float pxr = (float)(x + n%3) + ox;
            float fy = floorf(pyr), fx = floorf(pxr);
            float qy0 = fminf(fmaxf(fy,       0.f), 29.f);
            float qy1 = fminf(fmaxf(fy + 1.f, 0.f), 29.f);
            float qx0 = fminf(fmaxf(fx,       0.f), 29.f);
            float qx1 = fminf(fmaxf(fx + 1.f, 0.f), 29.f);
            float pyc = fminf(fmaxf(pyr, 0.f), 29.f);
            float pxc = fminf(fmaxf(pxr, 0.f), 29.f);
            float glt = (1.f + (qy0 - pyc)) * (1.f + (qx0 - pxc));
            float grb = (1.f - (qy1 - pyc)) * (1.f - (qx1 - pxc));
            float glb = (1.f + (qy0 - pyc)) * (1.f - (qx1 - pxc));
            float grt = (1.f - (qy1 - pyc)) * (1.f + (qx0 - pxc));
            int iy0 = (int)qy0, iy1 = (int)qy1, ix0 = (int)qx0, ix1 = (int)qx1;
            float v00 = img[(iy0*30+ix0)*32 + lane];
            float v11 = img[(iy1*30+ix1)*32 + lane];
            float v01 = img[(iy0*30+ix1)*32 + lane];
            float v10 = img[(iy1*30+ix0)*32 + lane];
            xsh[pl*288 + n*32 + lane] = glt*v00 + grb*v11 + glb*v01 + grt*v10;
        }
    }
    __syncthreads();

    // Phase B: 288 -> 32 GEMM, float4 k-quads
    int pbase = warp*7;
    float acc[7] = {0,0,0,0,0,0,0};
    const float4* xp0 = (const float4*)&xsh[pbase*288];
    #pragma unroll 4
    for (int nc4 = 0; nc4 < 72; nc4++) {
        float4 w = wsh[nc4*32 + lane];
        #pragma unroll
        for (int i = 0; i < 7; i++) {
            float4 a = xp0[i*72 + nc4];
            acc[i] = fmaf(a.x, w.x, acc[i]);
            acc[i] = fmaf(a.y, w.y, acc[i]);
            acc[i] = fmaf(a.z, w.z, acc[i]);
            acc[i] = fmaf(a.w, w.w, acc[i]);
        }
    }
    float inv = g2[lane] * rsqrtf(v2[lane] + 1e-5f);
    float sh  = b2_[lane] - m2[lane]*inv;
    #pragma unroll
    for (int i = 0; i < 7; i++) {
        int px = pbase + i;
        int y = y0 + px/28, x = px%28;
        g_h2p[((b*30+y+1)*30 + x+1)*32 + lane] = fmaxf(acc[i], 0.f)*inv + sh;
    }
}

// ---------------------------------------------------------------------------
// K4: conv3(32->64, pad1) + relu + partial pooled sum (bn folded into head)
// block = (image, 4-row strip), 128 threads. Both o-halves per lane.
// float4 act + 2x float4 weight loads, scalar FFMA; 7-px x 2-o tile.
// dyn smem: wshA+wshB float4[2*8*9*32] (73728B) + ash 6*30*32 (23040B) = 96768B
// ---------------------------------------------------------------------------
__global__ void k4_conv3(const float* __restrict__ w3) {
    extern __shared__ float sm4[];
    float4* wshA = (float4*)sm4;         // [(c4*9+t)*32+lane] = w[o=lane][4c4..+3]
    float4* wshB = wshA + 8*9*32;        // same for o=lane+32
    float*  ash  = sm4 + 2*4*8*9*32;     // [ry][x][c], 6x30x32
    __shared__ float red[64];
    int tid = threadIdx.x;
    int b = blockIdx.x / 7, strip = blockIdx.x % 7;
    for (int i = tid; i < 8*9*32; i += 128) {
        int lane = i & 31, t = (i >> 5) % 9, c4 = i / 288;
        wshA[i] = make_float4(w3[lane*288 + (4*c4+0)*9 + t], w3[lane*288 + (4*c4+1)*9 + t],
                              w3[lane*288 + (4*c4+2)*9 + t], w3[lane*288 + (4*c4+3)*9 + t]);
        wshB[i] = make_float4(w3[(lane+32)*288 + (4*c4+0)*9 + t], w3[(lane+32)*288 + (4*c4+1)*9 + t],
                              w3[(lane+32)*288 + (4*c4+2)*9 + t], w3[(lane+32)*288 + (4*c4+3)*9 + t]);
    }
    const float* src = &g_h2p[(b*30 + strip*4)*30*32];
    for (int i = tid; i < 6*30*32; i += 128) ash[i] = src[i];
    if (tid < 64) red[tid] = 0.f;
    __syncthreads();

    int warp = tid >> 5, lane = tid & 31;
    float s0 = 0.f, s1 = 0.f;
    for (int x0 = 0; x0 < 28; x0 += 7) {
        float a0[7] = {0,0,0,0,0,0,0};   // o = lane
        float a1[7] = {0,0,0,0,0,0,0};   // o = lane+32
        for (int t = 0; t < 9; t++) {
            int ty = t/3, tx = t%3;
            const float4* ap = (const float4*)&ash[((warp + ty)*30 + x0 + tx)*32];
            #pragma unroll
            for (int c4 = 0; c4 < 8; c4++) {
                float4 wA = wshA[(c4*9+t)*32 + lane];
                float4 wB = wshB[(c4*9+t)*32 + lane];
                #pragma unroll
                for (int i = 0; i < 7; i++) {
                    float4 a = ap[i*8 + c4];
                    a0[i] = fmaf(a.x, wA.x, a0[i]);
                    a1[i] = fmaf(a.x, wB.x, a1[i]);
                    a0[i] = fmaf(a.y, wA.y, a0[i]);
                    a1[i] = fmaf(a.y, wB.y, a1[i]);
                    a0[i] = fmaf(a.z, wA.z, a0[i]);
                    a1[i] = fmaf(a.z, wB.z, a1[i]);
                    a0[i] = fmaf(a.w, wA.w, a0[i]);
                    a1[i] = fmaf(a.w, wB.w, a1[i]);
                }
            }
        }
        #pragma unroll
        for (int i = 0; i < 7; i++) {
            s0 += fmaxf(a0[i], 0.f);
            s1 += fmaxf(a1[i], 0.f);
        }
    }
    atomicAdd(&red[lane],      s0);
    atomicAdd(&red[lane + 32], s1);
    __syncthreads();
    if (tid < 64) g_part[(b*7+strip)*64 + tid] = red[tid];
}

// ---------------------------------------------------------------------------
// K5: reduce partials -> mean -> bn3 -> linear(64->10) -> log_softmax
// ---------------------------------------------------------------------------
__global__ void k5_head(const float* __restrict__ g3, const float* __restrict__ b3,
                        const float* __restrict__ m3, const float* __restrict__ v3,
                        const float* __restrict__ wc, const float* __restrict__ bc,
                        float* __restrict__ out) {
    __shared__ float hsh[64];
    __shared__ float lg[10];
    int b = blockIdx.x, tid = threadIdx.x;
    if (tid < 64) {
        float s = 0.f;
        for (int k = 0; k < 7; k++) s += g_part[(b*7+k)*64 + tid];
        s *= (1.f/784.f);
        float inv = g3[tid] * rsqrtf(v3[tid] + 1e-5f);
        hsh[tid] = s * inv + (b3[tid] - m3[tid]*inv);
    }
    __syncthreads();
    if (tid < 10) {
        float acc = bc[tid];
        for (int o = 0; o < 64; o++) acc = fmaf(hsh[o], wc[tid*64 + o], acc);
        lg[tid] = acc;
    }
    __syncthreads();
    if (tid < 10) {
        float mx = -1e30f;
        for (int j = 0; j < 10; j++) mx = fmaxf(mx, lg[j]);
        float se = 0.f;
        for (int j = 0; j < 10; j++) se += expf(lg[j] - mx);
        out[b*10 + tid] = lg[tid] - mx - logf(se);
    }
}

// ---------------------------------------------------------------------------
extern "C" void kernel_launch(void* const* d_in, const int* in_sizes, int n_in,
                              void* d_out, int out_size) {
    const float* x  = (const float*)d_in[0];
    const float* w1 = (const float*)d_in[1];
    const float* g1 = (const float*)d_in[2];
    const float* b1 = (const float*)d_in[3];
    const float* m1 = (const float*)d_in[4];
    const float* v1 = (const float*)d_in[5];
    const float* wp = (const float*)d_in[6];
    const float* bp = (const float*)d_in[7];
    const float* w2 = (const float*)d_in[8];
    const float* g2 = (const float*)d_in[9];
    const float* b2 = (const float*)d_in[10];
    const float* m2 = (const float*)d_in[11];
    const float* v2 = (const float*)d_in[12];
    const float* w3 = (const float*)d_in[13];
    const float* g3 = (const float*)d_in[14];
    const float* b3 = (const float*)d_in[15];
    const float* m3 = (const float*)d_in[16];
    const float* v3 = (const float*)d_in[17];
    const float* wc = (const float*)d_in[18];
    const float* bc = (const float*)d_in[19];

    cudaFuncSetAttribute(k2_pconv,  cudaFuncAttributeMaxDynamicSharedMemorySize, 59904);
    cudaFuncSetAttribute(k3_deform, cudaFuncAttributeMaxDynamicSharedMemorySize, 101376);
    cudaFuncSetAttribute(k4_conv3,  cudaFuncAttributeMaxDynamicSharedMemorySize, 96768);

    k1_conv1<<<28800, 256>>>(x, w1, g1, b1, m1, v1);
    k2_pconv<<<BB*7, 128, 59904>>>(wp, bp);
    k3_deform<<<BB*14, 256, 101376>>>(w2, g2, b2, m2, v2);
    k4_conv3<<<BB*7, 128, 96768>>>(w3);
    k5_head<<<BB, 64>>>(g3, b3, m3, v3, wc, bc, (float*)d_out);
}